// round 10
// baseline (speedup 1.0000x reference)
#include <cuda_runtime.h>
#include <math.h>

// Problem constants (from reference)
#define S_GRID 14
#define NCLS   20
#define NBATCH 4096
#define NCELLS (NBATCH * S_GRID * S_GRID)   // 802816

#define NBLOCKS  1184     // 8 CTAs/SM * 148 SMs
#define NTHREADS 256

// Per-block partial sums: [block][0]=cls, [1]=noobj, [2]=contain, [3]=reg
__device__ float g_part[NBLOCKS * 4];

__global__ __launch_bounds__(NTHREADS) void yolo_main_kernel(
    const float* __restrict__ pred,          // (N,S,S,30)
    const float* __restrict__ tbox,          // (N,S,S,4)
    const float* __restrict__ tcls,          // (N,S,S,20)
    const int*   __restrict__ mask)          // (N,S,S) bool promoted to 32-bit
{
    float acc_cls = 0.f, acc_noobj = 0.f, acc_contain = 0.f, acc_reg = 0.f;

    const int stride = gridDim.x * blockDim.x;
    for (int cell = blockIdx.x * blockDim.x + threadIdx.x; cell < NCELLS; cell += stride) {
        // ---- loads ----
        // pred row stride = 120 B: 8-byte aligned for every cell, 16-byte only for
        // even cells -> float2 is the widest universally safe vector width.
        const float2* p2 = reinterpret_cast<const float2*>(pred + (size_t)cell * 30);
        float pv[30];
        #pragma unroll
        for (int i = 0; i < 15; i++) {
            float2 v = __ldg(p2 + i);
            pv[2 * i]     = v.x;
            pv[2 * i + 1] = v.y;
        }
        float4 tb = __ldg(reinterpret_cast<const float4*>(tbox + (size_t)cell * 4));
        // 32-bit read + "!= 0" test is correct whether the bool was promoted
        // to int32 (1) or float32 (0x3F800000).
        float m = (__ldg(mask + cell) != 0) ? 1.0f : 0.0f;

        // ---- class loss: sum over 20 classes of (pred_cls - target_cls)^2 ----
        const float4* tc4 = reinterpret_cast<const float4*>(tcls + (size_t)cell * 20);
        float cls = 0.f;
        #pragma unroll
        for (int i = 0; i < 5; i++) {
            float4 t = __ldg(tc4 + i);
            float a = pv[10 + 4 * i]     - t.x;
            float b = pv[10 + 4 * i + 1] - t.y;
            float c = pv[10 + 4 * i + 2] - t.z;
            float d = pv[10 + 4 * i + 3] - t.w;
            cls += a * a + b * b + c * c + d * d;
        }
        acc_cls += m * cls;

        // ---- no-object confidence loss (both boxes) ----
        float conf0 = pv[4], conf1 = pv[9];
        acc_noobj += (1.0f - m) * (conf0 * conf0 + conf1 * conf1);

        // ---- IoU for each of the 2 boxes vs target (x1,y1,x2,y2) ----
        float area_t = (tb.z - tb.x) * (tb.w - tb.y);
        float iou[2];
        #pragma unroll
        for (int b = 0; b < 2; b++) {
            float x = pv[5 * b + 0] * (1.0f / S_GRID);
            float y = pv[5 * b + 1] * (1.0f / S_GRID);
            float w = pv[5 * b + 2];
            float h = pv[5 * b + 3];
            float p1x = x - 0.5f * w, p1y = y - 0.5f * h;
            float p2x = x + 0.5f * w, p2y = y + 0.5f * h;
            float ltx = fmaxf(p1x, tb.x), lty = fmaxf(p1y, tb.y);
            float rbx = fminf(p2x, tb.z), rby = fminf(p2y, tb.w);
            float iw = fmaxf(rbx - ltx, 0.0f);
            float ih = fmaxf(rby - lty, 0.0f);
            float inter  = iw * ih;
            float area_p = w * h;
            iou[b] = inter / (area_p + area_t - inter);
        }
        // jnp.argmax: first max wins -> box 1 only if strictly greater
        int best = (iou[1] > iou[0]) ? 1 : 0;
        float bx = pv[5 * best + 0];
        float by = pv[5 * best + 1];
        float bw = pv[5 * best + 2];
        float bh = pv[5 * best + 3];
        float bc = pv[5 * best + 4];

        // ---- containing-object loss ----
        acc_contain += m * (bc - 1.0f) * (bc - 1.0f);

        // ---- regression loss (center uses RAW xy; dim uses sqrt of raw wh) ----
        float dx = bx - tb.x;
        float dy = by - tb.y;
        float dw = sqrtf(bw) - sqrtf(tb.z);
        float dh = sqrtf(bh) - sqrtf(tb.w);
        acc_reg += m * (dx * dx + dy * dy + dw * dw + dh * dh);
    }

    // ---- block reduction (warp shuffle + smem) ----
    #pragma unroll
    for (int o = 16; o > 0; o >>= 1) {
        acc_cls     += __shfl_down_sync(0xffffffffu, acc_cls, o);
        acc_noobj   += __shfl_down_sync(0xffffffffu, acc_noobj, o);
        acc_contain += __shfl_down_sync(0xffffffffu, acc_contain, o);
        acc_reg     += __shfl_down_sync(0xffffffffu, acc_reg, o);
    }
    __shared__ float sm[NTHREADS / 32][4];
    int warp = threadIdx.x >> 5;
    int lane = threadIdx.x & 31;
    if (lane == 0) {
        sm[warp][0] = acc_cls;
        sm[warp][1] = acc_noobj;
        sm[warp][2] = acc_contain;
        sm[warp][3] = acc_reg;
    }
    __syncthreads();
    if (threadIdx.x == 0) {
        float s0 = 0.f, s1 = 0.f, s2 = 0.f, s3 = 0.f;
        #pragma unroll
        for (int w = 0; w < NTHREADS / 32; w++) {
            s0 += sm[w][0]; s1 += sm[w][1]; s2 += sm[w][2]; s3 += sm[w][3];
        }
        g_part[4 * blockIdx.x + 0] = s0;
        g_part[4 * blockIdx.x + 1] = s1;
        g_part[4 * blockIdx.x + 2] = s2;
        g_part[4 * blockIdx.x + 3] = s3;
    }
}

__global__ __launch_bounds__(NTHREADS) void yolo_finalize_kernel(float* __restrict__ out)
{
    float s0 = 0.f, s1 = 0.f, s2 = 0.f, s3 = 0.f;
    for (int i = threadIdx.x; i < NBLOCKS; i += blockDim.x) {
        s0 += g_part[4 * i + 0];
        s1 += g_part[4 * i + 1];
        s2 += g_part[4 * i + 2];
        s3 += g_part[4 * i + 3];
    }
    #pragma unroll
    for (int o = 16; o > 0; o >>= 1) {
        s0 += __shfl_down_sync(0xffffffffu, s0, o);
        s1 += __shfl_down_sync(0xffffffffu, s1, o);
        s2 += __shfl_down_sync(0xffffffffu, s2, o);
        s3 += __shfl_down_sync(0xffffffffu, s3, o);
    }
    __shared__ float sm[NTHREADS / 32][4];
    int warp = threadIdx.x >> 5;
    int lane = threadIdx.x & 31;
    if (lane == 0) {
        sm[warp][0] = s0; sm[warp][1] = s1; sm[warp][2] = s2; sm[warp][3] = s3;
    }
    __syncthreads();
    if (threadIdx.x == 0) {
        float t0 = 0.f, t1 = 0.f, t2 = 0.f, t3 = 0.f;
        #pragma unroll
        for (int w = 0; w < NTHREADS / 32; w++) {
            t0 += sm[w][0]; t1 += sm[w][1]; t2 += sm[w][2]; t3 += sm[w][3];
        }
        const float inv_n = 1.0f / (float)NBATCH;
        float cls_loss     = t0 * inv_n;
        float no_obj_loss  = t1 * inv_n;
        float contain_loss = t2 * inv_n;
        float reg_loss     = t3 * inv_n;
        float total = cls_loss + 0.5f * no_obj_loss + 5.0f * reg_loss + contain_loss;
        out[0] = total;
        out[1] = reg_loss;
        out[2] = contain_loss;
        out[3] = no_obj_loss;
        out[4] = cls_loss;
    }
}

extern "C" void kernel_launch(void* const* d_in, const int* in_sizes, int n_in,
                              void* d_out, int out_size)
{
    const float* pred = (const float*)d_in[0];
    const float* tbox = (const float*)d_in[1];
    const float* tcls = (const float*)d_in[2];
    const int*   mask = (const int*)d_in[3];
    float* out = (float*)d_out;

    yolo_main_kernel<<<NBLOCKS, NTHREADS>>>(pred, tbox, tcls, mask);
    yolo_finalize_kernel<<<1, NTHREADS>>>(out);
}